// round 5
// baseline (speedup 1.0000x reference)
#include <cuda_runtime.h>
#include <cuda_bf16.h>

#define DEV_INLINE __device__ __forceinline__
constexpr int BATCH = 4;

// ---------------- buffer layout (floats, inside g_buf) --------------------
// 32/16 res: NCHW padded (halo 1). 8/4/2 res: NHWC padded. Fixed channel caps.
constexpr int OFF_X    = 0;                         // [4][3][34][34]
constexpr int SZ_X     = BATCH * 3 * 34 * 34;
constexpr int OFF_32A  = OFF_X + SZ_X;              // cap 64
constexpr int SZ_32    = BATCH * 64 * 34 * 34;
constexpr int OFF_32B  = OFF_32A + SZ_32;
constexpr int OFF_16A  = OFF_32B + SZ_32;           // cap 128
constexpr int SZ_16    = BATCH * 128 * 18 * 18;
constexpr int OFF_16B  = OFF_16A + SZ_16;
constexpr int OFF_8A   = OFF_16B + SZ_16;           // NHWC cap 256
constexpr int SZ_8     = BATCH * 10 * 10 * 256;
constexpr int OFF_8B   = OFF_8A + SZ_8;
constexpr int OFF_4A   = OFF_8B + SZ_8;             // NHWC cap 512
constexpr int SZ_4     = BATCH * 6 * 6 * 512;
constexpr int OFF_4B   = OFF_4A + SZ_4;
constexpr int OFF_2A   = OFF_4B + SZ_4;             // NHWC cap 512
constexpr int SZ_2     = BATCH * 4 * 4 * 512;
constexpr int OFF_2B   = OFF_2A + SZ_2;
constexpr int OFF_FLAT = OFF_2B + SZ_2;             // [4][2048]
constexpr int OFF_FCS0 = OFF_FLAT + BATCH * 2048;   // [4][4096]
constexpr int OFF_FCS1 = OFF_FCS0 + BATCH * 4096;

// membranes: conv 0-3 NCHW, conv 4-12 NHWC, fc [B][4096]
constexpr int M0  = OFF_FCS1 + BATCH * 4096;
constexpr int M1  = M0  + BATCH * 64  * 32 * 32;
constexpr int M2  = M1  + BATCH * 64  * 32 * 32;
constexpr int M3  = M2  + BATCH * 128 * 16 * 16;
constexpr int M4  = M3  + BATCH * 128 * 16 * 16;
constexpr int M5  = M4  + BATCH * 256 * 8 * 8;
constexpr int M6  = M5  + BATCH * 256 * 8 * 8;
constexpr int M7  = M6  + BATCH * 256 * 8 * 8;
constexpr int M8  = M7  + BATCH * 512 * 4 * 4;
constexpr int M9  = M8  + BATCH * 512 * 4 * 4;
constexpr int M10 = M9  + BATCH * 512 * 4 * 4;
constexpr int M11 = M10 + BATCH * 512 * 2 * 2;
constexpr int M12 = M11 + BATCH * 512 * 2 * 2;
constexpr int MF0 = M12 + BATCH * 512 * 2 * 2;
constexpr int MF1 = MF0 + BATCH * 4096;
constexpr int TOTAL_BUF = MF1 + BATCH * 4096;

__device__ __align__(16) float g_buf[TOTAL_BUF];

// transposed weights [co][tap][ci] for conv layers 4..12
constexpr int WT4  = 0;
constexpr int WT5  = WT4  + 256 * 128 * 9;
constexpr int WT6  = WT5  + 256 * 256 * 9;
constexpr int WT7  = WT6  + 256 * 256 * 9;
constexpr int WT8  = WT7  + 512 * 256 * 9;
constexpr int WT9  = WT8  + 512 * 512 * 9;
constexpr int WT10 = WT9  + 512 * 512 * 9;
constexpr int WT11 = WT10 + 512 * 512 * 9;
constexpr int WT12 = WT11 + 512 * 512 * 9;
constexpr int WT_TOTAL = WT12 + 512 * 512 * 9;
__device__ float g_wt[WT_TOTAL];

// ---------------- multi-compartment LIF (K=2), exact match ----------------
// fire1 (val 1): m > thr  && m <= 2*thr ; fire2 (val 2): m > 2*thr && m <= 4*thr
DEV_INLINE float lif_fire(float* memp, float syn, float thr, float leak) {
    float m = leak * (*memp) + syn;
    float e0 = m / thr          - 1.0f;
    float o0 = 1.0f - m / (2.0f * thr);
    float e1 = m / (2.0f * thr) - 1.0f;
    float o1 = 1.0f - m / (4.0f * thr);
    float v = 0.0f;
    if (e0 > 0.0f && o0 >= 0.0f) v = 1.0f;
    if (e1 > 0.0f && o1 >= 0.0f) v = 2.0f;
    *memp = m - thr * v;
    return v;
}

// ---------------- housekeeping --------------------------------------------
__global__ void k_zero(float* __restrict__ dout) {
    int i = blockIdx.x * blockDim.x + threadIdx.x;
    if (i < TOTAL_BUF) g_buf[i] = 0.0f;
    if (i < BATCH * 10) dout[i] = 0.0f;
}

__global__ void k_pad_x(const float* __restrict__ x) {
    int idx = blockIdx.x * blockDim.x + threadIdx.x;
    if (idx >= BATCH * 3 * 32 * 32) return;
    int xx = idx & 31;
    int y  = (idx >> 5) & 31;
    int c  = (idx >> 10) % 3;
    int b  = idx / (3 * 1024);
    g_buf[OFF_X + ((b * 3 + c) * 34 + (y + 1)) * 34 + (xx + 1)] = x[idx];
}

// [co][ci][9] -> [co][9][ci]
__global__ void k_wtrans(const float* __restrict__ w, int wt_off, int CIN) {
    __shared__ float s[512 * 9];
    int co = blockIdx.x;
    const float* src = w + (long)co * CIN * 9;
    float* dst = g_wt + wt_off + (long)co * CIN * 9;
    for (int i = threadIdx.x; i < CIN * 9; i += blockDim.x) s[i] = src[i];
    __syncthreads();
    for (int i = threadIdx.x; i < CIN * 9; i += blockDim.x) {
        int ci = i % CIN, t = i / CIN;
        dst[i] = s[ci * 9 + t];
    }
}

// ---------------- conv flavor T: NCHW, thread does TX outputs -------------
template<int CIN, int CICAP, int S, int TX>
__global__ __launch_bounds__(256)
void k_conv_T(int in_off, const float* __restrict__ w, int mem_off, int out_off,
              const float* __restrict__ thrp, const float* __restrict__ leakp,
              int Cout) {
    constexpr int SP = S + 2;
    constexpr int NX = S / TX;
    int idx = blockIdx.x * blockDim.x + threadIdx.x;
    if (idx >= BATCH * Cout * S * NX) return;
    int x0 = (idx % NX) * TX;
    int y  = (idx / NX) % S;
    int co = (idx / (NX * S)) % Cout;
    int b  = idx / (NX * S * Cout);

    const float* wp = w + (long)co * CIN * 9;
    const float* ip = g_buf + in_off + (long)b * CICAP * SP * SP + y * SP + x0;

    float acc[TX];
#pragma unroll
    for (int t = 0; t < TX; t++) acc[t] = 0.0f;

    for (int ci = 0; ci < CIN; ci++) {
        const float* icp = ip + ci * SP * SP;
        float r0[TX + 2], r1[TX + 2], r2[TX + 2];
#pragma unroll
        for (int j = 0; j < TX + 2; j++) {
            r0[j] = __ldg(icp + j);
            r1[j] = __ldg(icp + SP + j);
            r2[j] = __ldg(icp + 2 * SP + j);
        }
        float wv[9];
#pragma unroll
        for (int t = 0; t < 9; t++) wv[t] = __ldg(wp + ci * 9 + t);
#pragma unroll
        for (int t = 0; t < TX; t++)
            acc[t] += wv[0]*r0[t] + wv[1]*r0[t+1] + wv[2]*r0[t+2]
                    + wv[3]*r1[t] + wv[4]*r1[t+1] + wv[5]*r1[t+2]
                    + wv[6]*r2[t] + wv[7]*r2[t+1] + wv[8]*r2[t+2];
    }

    float thr = __ldg(thrp), leak = __ldg(leakp);
    long mbase = (((long)b * Cout + co) * S + y) * S + x0;
    long obase = (((long)b * Cout + co) * SP + (y + 1)) * SP + (x0 + 1);
#pragma unroll
    for (int t = 0; t < TX; t++)
        g_buf[out_off + obase + t] =
            lif_fire(&g_buf[mem_off + mbase + t], acc[t], thr, leak);
}

// ---------------- conv flavor W: NHWC, warp per (b,co,row) ----------------
template<int CIN, int CST, int S>
__global__ __launch_bounds__(256)
void k_conv_W(int in_off, int wt_off, int mem_off, int out_off,
              const float* __restrict__ thrp, const float* __restrict__ leakp,
              int Cout) {
    constexpr int SP = S + 2;
    int gt = blockIdx.x * blockDim.x + threadIdx.x;
    int gw = gt >> 5, lane = gt & 31;
    if (gw >= BATCH * Cout * S) return;
    int y  = gw % S;
    int co = (gw / S) % Cout;
    int b  = gw / (S * Cout);

    const float* wq  = g_wt + wt_off + (long)co * CIN * 9;          // [tap][ci]
    const float* icp = g_buf + in_off + ((long)b * SP + y) * SP * CST;

    float acc[S];
#pragma unroll
    for (int t = 0; t < S; t++) acc[t] = 0.0f;

    for (int ci = lane; ci < CIN; ci += 32) {
        float wv[9];
#pragma unroll
        for (int t = 0; t < 9; t++) wv[t] = __ldg(wq + t * CIN + ci);
        float r0[S + 2], r1[S + 2], r2[S + 2];
#pragma unroll
        for (int j = 0; j < S + 2; j++) {
            r0[j] = __ldg(icp + j * CST + ci);
            r1[j] = __ldg(icp + (SP + j) * CST + ci);
            r2[j] = __ldg(icp + (2 * SP + j) * CST + ci);
        }
#pragma unroll
        for (int t = 0; t < S; t++)
            acc[t] += wv[0]*r0[t] + wv[1]*r0[t+1] + wv[2]*r0[t+2]
                    + wv[3]*r1[t] + wv[4]*r1[t+1] + wv[5]*r1[t+2]
                    + wv[6]*r2[t] + wv[7]*r2[t+1] + wv[8]*r2[t+2];
    }
#pragma unroll
    for (int t = 0; t < S; t++)
#pragma unroll
        for (int o = 16; o; o >>= 1)
            acc[t] += __shfl_xor_sync(0xffffffffu, acc[t], o);

    if (lane == 0) {
        float thr = __ldg(thrp), leak = __ldg(leakp);
#pragma unroll
        for (int t = 0; t < S; t++) {
            long midx = (((long)b * S + y) * S + t) * Cout + co;
            long oidx = (((long)b * SP + (y + 1)) * SP + (t + 1)) * (long)Cout + co;
            g_buf[out_off + oidx] =
                lif_fire(&g_buf[mem_off + midx], acc[t], thr, leak);
        }
    }
}

// ---------------- avg-pool 2x2 (three layout flavors) ---------------------
template<int C, int S, int CI, int CO>  // NCHW -> NCHW (S = input size)
__global__ void k_pool_cc(int in_off, int out_off) {
    constexpr int SO = S / 2, SPI = S + 2, SPO = SO + 2;
    int idx = blockIdx.x * blockDim.x + threadIdx.x;
    if (idx >= BATCH * C * SO * SO) return;
    int x = idx % SO, y = (idx / SO) % SO;
    int c = (idx / (SO * SO)) % C, b = idx / (SO * SO * C);
    const float* p = g_buf + in_off + ((long)(b * CI + c) * SPI + 2 * y + 1) * SPI + 2 * x + 1;
    float v = 0.25f * (p[0] + p[1] + p[SPI] + p[SPI + 1]);
    g_buf[out_off + ((long)(b * CO + c) * SPO + y + 1) * SPO + x + 1] = v;
}

template<int C, int S, int CI, int CSTO>  // NCHW -> NHWC
__global__ void k_pool_cn(int in_off, int out_off) {
    constexpr int SO = S / 2, SPI = S + 2, SPO = SO + 2;
    int idx = blockIdx.x * blockDim.x + threadIdx.x;
    if (idx >= BATCH * C * SO * SO) return;
    int c = idx % C;
    int x = (idx / C) % SO, y = (idx / (C * SO)) % SO, b = idx / (C * SO * SO);
    const float* p = g_buf + in_off + ((long)(b * CI + c) * SPI + 2 * y + 1) * SPI + 2 * x + 1;
    float v = 0.25f * (p[0] + p[1] + p[SPI] + p[SPI + 1]);
    g_buf[out_off + (((long)b * SPO + y + 1) * SPO + x + 1) * CSTO + c] = v;
}

template<int C, int S, int CSTI, int CSTO>  // NHWC -> NHWC
__global__ void k_pool_nn(int in_off, int out_off) {
    constexpr int SO = S / 2, SPI = S + 2, SPO = SO + 2;
    int idx = blockIdx.x * blockDim.x + threadIdx.x;
    if (idx >= BATCH * C * SO * SO) return;
    int c = idx % C;
    int x = (idx / C) % SO, y = (idx / (C * SO)) % SO, b = idx / (C * SO * SO);
    const float* p = g_buf + in_off + (((long)b * SPI + 2 * y + 1) * SPI + 2 * x + 1) * CSTI + c;
    float v = 0.25f * (p[0] + p[CSTI] + p[SPI * (long)CSTI] + p[(SPI + 1) * (long)CSTI]);
    g_buf[out_off + (((long)b * SPO + y + 1) * SPO + x + 1) * CSTO + c] = v;
}

// ---------------- flatten: NHWC padded [B,4,4,512] -> [B][c*4+y*2+x] ------
__global__ void k_flatten() {
    int idx = blockIdx.x * blockDim.x + threadIdx.x;
    if (idx >= BATCH * 2048) return;
    int f = idx % 2048, b = idx / 2048;
    int c = f >> 2, y = (f >> 1) & 1, x = f & 1;
    g_buf[OFF_FLAT + idx] =
        g_buf[OFF_2B + (((long)(b * 4) + y + 1) * 4 + (x + 1)) * 512 + c];
}

// ---------------- fully connected (warp per output) -----------------------
template<int KD>
__global__ __launch_bounds__(256)
void k_fc_lif(int in_off, const float* __restrict__ W, int mem_off,
              int out_off, const float* __restrict__ thrp,
              const float* __restrict__ leakp, int OUTN) {
    int gt = blockIdx.x * blockDim.x + threadIdx.x;
    int gw = gt >> 5, lane = gt & 31;
    if (gw >= BATCH * OUTN) return;
    int o = gw % OUTN, b = gw / OUTN;
    const float4* ip = (const float4*)(g_buf + in_off + (long)b * KD);
    const float4* wp = (const float4*)(W + (long)o * KD);
    float acc = 0.0f;
#pragma unroll 4
    for (int k = lane; k < KD / 4; k += 32) {
        float4 a = __ldg(ip + k), w = __ldg(wp + k);
        acc += a.x * w.x + a.y * w.y + a.z * w.z + a.w * w.w;
    }
#pragma unroll
    for (int of = 16; of; of >>= 1) acc += __shfl_xor_sync(0xffffffffu, acc, of);
    if (lane == 0) {
        float thr = __ldg(thrp), leak = __ldg(leakp);
        g_buf[out_off + (long)b * OUTN + o] =
            lif_fire(&g_buf[mem_off + (long)b * OUTN + o], acc, thr, leak);
    }
}

__global__ void k_fc_logits(int in_off, const float* __restrict__ W,
                            float* __restrict__ dout) {
    int gt = blockIdx.x * blockDim.x + threadIdx.x;
    int gw = gt >> 5, lane = gt & 31;
    if (gw >= BATCH * 10) return;
    int o = gw % 10, b = gw / 10;
    const float4* ip = (const float4*)(g_buf + in_off + (long)b * 4096);
    const float4* wp = (const float4*)(W + (long)o * 4096);
    float acc = 0.0f;
#pragma unroll 4
    for (int k = lane; k < 1024; k += 32) {
        float4 a = __ldg(ip + k), w = __ldg(wp + k);
        acc += a.x * w.x + a.y * w.y + a.z * w.z + a.w * w.w;
    }
#pragma unroll
    for (int of = 16; of; of >>= 1) acc += __shfl_xor_sync(0xffffffffu, acc, of);
    if (lane == 0) dout[b * 10 + o] += acc;
}

// ---------------- launch --------------------------------------------------
static inline int gup(long n, int b) { return (int)((n + b - 1) / b); }

extern "C" void kernel_launch(void* const* d_in, const int* in_sizes, int n_in,
                              void* d_out, int out_size) {
    const float* x   = (const float*)d_in[0];
    const float* w[13];
    for (int i = 0; i < 13; i++) w[i] = (const float*)d_in[1 + i];
    const float* fc0  = (const float*)d_in[14];
    const float* fc1  = (const float*)d_in[15];
    const float* fc2  = (const float*)d_in[16];
    const float* thr  = (const float*)d_in[17];
    const float* leak = (const float*)d_in[18];
    float* out = (float*)d_out;

    k_zero<<<gup(TOTAL_BUF, 256), 256>>>(out);
    k_pad_x<<<gup(BATCH * 3 * 1024, 256), 256>>>(x);

    // weight transposes for warp-flavor layers 4..12
    k_wtrans<<<256, 256>>>(w[4],  WT4,  128);
    k_wtrans<<<256, 256>>>(w[5],  WT5,  256);
    k_wtrans<<<256, 256>>>(w[6],  WT6,  256);
    k_wtrans<<<512, 256>>>(w[7],  WT7,  256);
    k_wtrans<<<512, 256>>>(w[8],  WT8,  512);
    k_wtrans<<<512, 256>>>(w[9],  WT9,  512);
    k_wtrans<<<512, 256>>>(w[10], WT10, 512);
    k_wtrans<<<512, 256>>>(w[11], WT11, 512);
    k_wtrans<<<512, 256>>>(w[12], WT12, 512);

    for (int t = 0; t < 3; t++) {
        // ---- 32x32, NCHW, TX=4 ----
        k_conv_T<3, 3, 32, 4><<<gup(4L*64*32*8, 256), 256>>>(
            OFF_X, w[0], M0, OFF_32A, thr + 0, leak + 0, 64);
        k_conv_T<64, 64, 32, 4><<<gup(4L*64*32*8, 256), 256>>>(
            OFF_32A, w[1], M1, OFF_32B, thr + 1, leak + 1, 64);
        k_pool_cc<64, 32, 64, 128><<<gup(4L*64*16*16, 256), 256>>>(OFF_32B, OFF_16A);

        // ---- 16x16, NCHW, TX=2 ----
        k_conv_T<64, 128, 16, 2><<<gup(4L*128*16*8, 256), 256>>>(
            OFF_16A, w[2], M2, OFF_16B, thr + 2, leak + 2, 128);
        k_conv_T<128, 128, 16, 2><<<gup(4L*128*16*8, 256), 256>>>(
            OFF_16B, w[3], M3, OFF_16A, thr + 3, leak + 3, 128);
        k_pool_cn<128, 16, 128, 256><<<gup(4L*128*8*8, 256), 256>>>(OFF_16A, OFF_8A);

        // ---- 8x8, NHWC, warp flavor ----
        k_conv_W<128, 256, 8><<<gup(4L*256*8*32, 256), 256>>>(
            OFF_8A, WT4, M4, OFF_8B, thr + 4, leak + 4, 256);
        k_conv_W<256, 256, 8><<<gup(4L*256*8*32, 256), 256>>>(
            OFF_8B, WT5, M5, OFF_8A, thr + 5, leak + 5, 256);
        k_conv_W<256, 256, 8><<<gup(4L*256*8*32, 256), 256>>>(
            OFF_8A, WT6, M6, OFF_8B, thr + 6, leak + 6, 256);
        k_pool_nn<256, 8, 256, 512><<<gup(4L*256*4*4, 256), 256>>>(OFF_8B, OFF_4A);

        // ---- 4x4, NHWC ----
        k_conv_W<256, 512, 4><<<gup(4L*512*4*32, 256), 256>>>(
            OFF_4A, WT7, M7, OFF_4B, thr + 7, leak + 7, 512);
        k_conv_W<512, 512, 4><<<gup(4L*512*4*32, 256), 256>>>(
            OFF_4B, WT8, M8, OFF_4A, thr + 8, leak + 8, 512);
        k_conv_W<512, 512, 4><<<gup(4L*512*4*32, 256), 256>>>(
            OFF_4A, WT9, M9, OFF_4B, thr + 9, leak + 9, 512);
        k_pool_nn<512, 4, 512, 512><<<gup(4L*512*2*2, 256), 256>>>(OFF_4B, OFF_2A);

        // ---- 2x2, NHWC ----
        k_conv_W<512, 512, 2><<<gup(4L*512*2*32, 256), 256>>>(
            OFF_2A, WT10, M10, OFF_2B, thr + 10, leak + 10, 512);
        k_conv_W<512, 512, 2><<<gup(4L*512*2*32, 256), 256>>>(
            OFF_2B, WT11, M11, OFF_2A, thr + 11, leak + 11, 512);
        k_conv_W<512, 512, 2><<<gup(4L*512*2*32, 256), 256>>>(
            OFF_2A, WT12, M12, OFF_2B, thr + 12, leak + 12, 512);

        // ---- classifier ----
        k_flatten<<<gup(4L*2048, 256), 256>>>();
        k_fc_lif<2048><<<gup(4L*4096*32, 256), 256>>>(
            OFF_FLAT, fc0, MF0, OFF_FCS0, thr + 13, leak + 13, 4096);
        k_fc_lif<4096><<<gup(4L*4096*32, 256), 256>>>(
            OFF_FCS0, fc1, MF1, OFF_FCS1, thr + 14, leak + 14, 4096);
        k_fc_logits<<<gup(4L*10*32, 256), 256>>>(OFF_FCS1, fc2, out);
    }
}

// round 6
// speedup vs baseline: 1.1478x; 1.1478x over previous
#include <cuda_runtime.h>
#include <cuda_bf16.h>

#define DEV_INLINE __device__ __forceinline__
constexpr int BATCH = 4;

// ---------------- buffer layout (floats) ----------------------------------
// NCHW padded: rows S+2, row-stride S+4 (36 / 20) so float4 loads stay aligned.
// NHWC padded: [B][S+2][S+2][CST].
constexpr int OFF_X    = 0;                         // [4][3][34][36]
constexpr int SZ_X     = BATCH * 3 * 34 * 36;
constexpr int OFF_32A  = OFF_X + SZ_X;              // cap 64
constexpr int SZ_32    = BATCH * 64 * 34 * 36;
constexpr int OFF_32B  = OFF_32A + SZ_32;
constexpr int OFF_16A  = OFF_32B + SZ_32;           // cap 128
constexpr int SZ_16    = BATCH * 128 * 18 * 20;
constexpr int OFF_16B  = OFF_16A + SZ_16;
constexpr int OFF_8A   = OFF_16B + SZ_16;           // NHWC [4][10][10][256]
constexpr int SZ_8     = BATCH * 10 * 10 * 256;
constexpr int OFF_8B   = OFF_8A + SZ_8;
constexpr int OFF_4A   = OFF_8B + SZ_8;             // NHWC [4][6][6][512]
constexpr int SZ_4     = BATCH * 6 * 6 * 512;
constexpr int OFF_4B   = OFF_4A + SZ_4;
constexpr int OFF_2A   = OFF_4B + SZ_4;             // NHWC [4][4][4][512]
constexpr int SZ_2     = BATCH * 4 * 4 * 512;
constexpr int OFF_2B   = OFF_2A + SZ_2;
constexpr int OFF_FCS0 = OFF_2B + SZ_2;             // [4][4096]
constexpr int OFF_FCS1 = OFF_FCS0 + BATCH * 4096;

// membranes: conv 0-3 NCHW dense, conv 4-12 NHWC dense, fc [B][4096]
constexpr int M0  = OFF_FCS1 + BATCH * 4096;
constexpr int M1  = M0  + BATCH * 64  * 32 * 32;
constexpr int M2  = M1  + BATCH * 64  * 32 * 32;
constexpr int M3  = M2  + BATCH * 128 * 16 * 16;
constexpr int M4  = M3  + BATCH * 128 * 16 * 16;
constexpr int M5  = M4  + BATCH * 256 * 8 * 8;
constexpr int M6  = M5  + BATCH * 256 * 8 * 8;
constexpr int M7  = M6  + BATCH * 256 * 8 * 8;
constexpr int M8  = M7  + BATCH * 512 * 4 * 4;
constexpr int M9  = M8  + BATCH * 512 * 4 * 4;
constexpr int M10 = M9  + BATCH * 512 * 4 * 4;
constexpr int M11 = M10 + BATCH * 512 * 2 * 2;
constexpr int M12 = M11 + BATCH * 512 * 2 * 2;
constexpr int MF0 = M12 + BATCH * 512 * 2 * 2;
constexpr int MF1 = MF0 + BATCH * 4096;
constexpr int TOTAL_BUF = MF1 + BATCH * 4096;

__device__ __align__(16) float g_buf[TOTAL_BUF];

// transposed weights [co][tap][ci] for conv layers 4..12
constexpr long WT4  = 0;
constexpr long WT5  = WT4  + 256L * 128 * 9;
constexpr long WT6  = WT5  + 256L * 256 * 9;
constexpr long WT7  = WT6  + 256L * 256 * 9;
constexpr long WT8  = WT7  + 512L * 256 * 9;
constexpr long WT9  = WT8  + 512L * 512 * 9;
constexpr long WT10 = WT9  + 512L * 512 * 9;
constexpr long WT11 = WT10 + 512L * 512 * 9;
constexpr long WT12 = WT11 + 512L * 512 * 9;
constexpr long WT_TOTAL = WT12 + 512L * 512 * 9;
__device__ __align__(16) float g_wt[WT_TOTAL];

// ---------------- multi-compartment LIF (K=2), exact ----------------------
DEV_INLINE float lif_fire(float* memp, float syn, float thr, float leak) {
    float m = leak * (*memp) + syn;
    float e0 = m / thr          - 1.0f;
    float o0 = 1.0f - m / (2.0f * thr);
    float e1 = m / (2.0f * thr) - 1.0f;
    float o1 = 1.0f - m / (4.0f * thr);
    float v = 0.0f;
    if (e0 > 0.0f && o0 >= 0.0f) v = 1.0f;
    if (e1 > 0.0f && o1 >= 0.0f) v = 2.0f;
    *memp = m - thr * v;
    return v;
}

// ---------------- housekeeping --------------------------------------------
__global__ void k_zero(float* __restrict__ dout) {
    int i = blockIdx.x * blockDim.x + threadIdx.x;
    if (i < TOTAL_BUF) g_buf[i] = 0.0f;
    if (i < BATCH * 10) dout[i] = 0.0f;
}

__global__ void k_pad_x(const float* __restrict__ x) {
    int idx = blockIdx.x * blockDim.x + threadIdx.x;
    if (idx >= BATCH * 3 * 32 * 32) return;
    int xx = idx & 31;
    int y  = (idx >> 5) & 31;
    int c  = (idx >> 10) % 3;
    int b  = idx / (3 * 1024);
    g_buf[OFF_X + ((b * 3 + c) * 34 + (y + 1)) * 36 + (xx + 1)] = x[idx];
}

// fused weight transpose for layers 4..12: [co][ci][9] -> [co][9][ci]
struct WP { const float* p[9]; };
__global__ void k_wtrans_all(WP wp) {
    __shared__ float s[4608];
    const int CINs[9]  = {128, 256, 256, 256, 512, 512, 512, 512, 512};
    const int COUTs[9] = {256, 256, 256, 512, 512, 512, 512, 512, 512};
    const long OFFs[9] = {WT4, WT5, WT6, WT7, WT8, WT9, WT10, WT11, WT12};
    int l  = blockIdx.y;
    int co = blockIdx.x;
    int CIN = CINs[l];
    if (co >= COUTs[l]) return;
    const float* src = wp.p[l] + (long)co * CIN * 9;
    float* dst = g_wt + OFFs[l] + (long)co * CIN * 9;
    int n = CIN * 9;
    for (int i = threadIdx.x; i < n; i += 256) s[i] = src[i];
    __syncthreads();
    for (int i = threadIdx.x; i < n; i += 256) {
        int ci = i % CIN, t = i / CIN;
        dst[i] = s[ci * 9 + t];
    }
}

// ---------------- conv flavor T: NCHW, one co per block, smem weights -----
// thread computes 4 x-adjacent outputs via float4 activation loads.
template<int CIN, int CICAP, int S, int COUT, int BLKS>
__global__ __launch_bounds__(256)
void k_conv_T(int in_off, const float* __restrict__ w, int mem_off, int out_off,
              const float* __restrict__ thrp, const float* __restrict__ leakp) {
    constexpr int RS = S + 4, ROWS = S + 2, NX = S / 4;
    constexpr int PLANE = ROWS * RS;
    __shared__ float sw[CIN * 12];
    int co   = blockIdx.x / BLKS;
    int part = blockIdx.x % BLKS;
    for (int i = threadIdx.x; i < CIN * 9; i += 256)
        sw[(i / 9) * 12 + (i % 9)] = w[(long)co * CIN * 9 + i];
    __syncthreads();

    int tid = part * 256 + threadIdx.x;
    int x0 = (tid % NX) * 4;
    int y  = (tid / NX) % S;
    int b  = tid / (NX * S);

    const float* ip = g_buf + in_off + (long)b * CICAP * PLANE + y * RS + x0;
    float acc[4] = {0.f, 0.f, 0.f, 0.f};

    for (int ci = 0; ci < CIN; ci++) {
        const float* p = ip + ci * PLANE;
        float r[3][8];
#pragma unroll
        for (int rr = 0; rr < 3; rr++) {
            float4 a = __ldg((const float4*)(p + rr * RS));
            float4 c = __ldg((const float4*)(p + rr * RS + 4));
            r[rr][0] = a.x; r[rr][1] = a.y; r[rr][2] = a.z; r[rr][3] = a.w;
            r[rr][4] = c.x; r[rr][5] = c.y; r[rr][6] = c.z; r[rr][7] = c.w;
        }
        float4 wa = *(const float4*)(sw + ci * 12);
        float4 wb = *(const float4*)(sw + ci * 12 + 4);
        float4 wc = *(const float4*)(sw + ci * 12 + 8);
        float wv[9] = {wa.x, wa.y, wa.z, wa.w, wb.x, wb.y, wb.z, wb.w, wc.x};
#pragma unroll
        for (int t = 0; t < 4; t++)
            acc[t] += wv[0]*r[0][t] + wv[1]*r[0][t+1] + wv[2]*r[0][t+2]
                    + wv[3]*r[1][t] + wv[4]*r[1][t+1] + wv[5]*r[1][t+2]
                    + wv[6]*r[2][t] + wv[7]*r[2][t+1] + wv[8]*r[2][t+2];
    }

    float thr = __ldg(thrp), leak = __ldg(leakp);
    long mbase = (((long)b * COUT + co) * S + y) * S + x0;
    long obase = (((long)b * COUT + co) * ROWS + (y + 1)) * RS + (x0 + 1);
#pragma unroll
    for (int t = 0; t < 4; t++)
        g_buf[out_off + obase + t] =
            lif_fire(&g_buf[mem_off + mbase + t], acc[t], thr, leak);
}

// ---------------- conv flavor W: NHWC, warp per (b,co,row), ci×4 vector ---
template<int CIN, int CST, int S, int COUT>
__global__ __launch_bounds__(256)
void k_conv_W(int in_off, long wt_off, int mem_off, int out_off,
              const float* __restrict__ thrp, const float* __restrict__ leakp) {
    constexpr int SP = S + 2;
    int gt = blockIdx.x * blockDim.x + threadIdx.x;
    int gw = gt >> 5, lane = gt & 31;
    if (gw >= BATCH * COUT * S) return;
    int y  = gw % S;
    int co = (gw / S) % COUT;
    int b  = gw / (S * COUT);

    const float* wq = g_wt + wt_off + (long)co * CIN * 9;   // [tap][ci]
    float acc[S];
#pragma unroll
    for (int t = 0; t < S; t++) acc[t] = 0.0f;

#pragma unroll
    for (int it = 0; it < CIN / 128; it++) {
        int cb = it * 128 + lane * 4;
        float4 wv[9];
#pragma unroll
        for (int t = 0; t < 9; t++)
            wv[t] = __ldg((const float4*)(wq + t * CIN + cb));
#pragma unroll
        for (int rr = 0; rr < 3; rr++) {
            const float* rp = g_buf + in_off + ((long)(b * SP + y + rr) * SP) * CST + cb;
#pragma unroll
            for (int j = 0; j < SP; j++) {
                float4 a = __ldg((const float4*)(rp + j * CST));
#pragma unroll
                for (int dx = 0; dx < 3; dx++) {
                    int t = j - dx;
                    if (t >= 0 && t < S) {
                        float4 wt = wv[rr * 3 + dx];
                        acc[t] += a.x*wt.x + a.y*wt.y + a.z*wt.z + a.w*wt.w;
                    }
                }
            }
        }
    }
#pragma unroll
    for (int t = 0; t < S; t++)
#pragma unroll
        for (int o = 16; o; o >>= 1)
            acc[t] += __shfl_xor_sync(0xffffffffu, acc[t], o);

    if (lane == 0) {
        float thr = __ldg(thrp), leak = __ldg(leakp);
#pragma unroll
        for (int t = 0; t < S; t++) {
            long midx = (((long)b * S + y) * S + t) * COUT + co;
            long oidx = (((long)b * SP + (y + 1)) * SP + (t + 1)) * (long)COUT + co;
            g_buf[out_off + oidx] =
                lif_fire(&g_buf[mem_off + midx], acc[t], thr, leak);
        }
    }
}

// ---------------- conv flavor W2: S=2, warp per (b,co), full image --------
template<int CIN>
__global__ __launch_bounds__(256)
void k_conv_W2(int in_off, long wt_off, int mem_off, int out_off,
               const float* __restrict__ thrp, const float* __restrict__ leakp) {
    constexpr int CST = 512, SP = 4, COUT = 512;
    int gt = blockIdx.x * blockDim.x + threadIdx.x;
    int gw = gt >> 5, lane = gt & 31;
    if (gw >= BATCH * COUT) return;
    int co = gw % COUT;
    int b  = gw / COUT;

    const float* wq = g_wt + wt_off + (long)co * CIN * 9;
    float acc[2][2] = {{0.f, 0.f}, {0.f, 0.f}};

#pragma unroll
    for (int it = 0; it < CIN / 128; it++) {
        int cb = it * 128 + lane * 4;
        float4 wv[9];
#pragma unroll
        for (int t = 0; t < 9; t++)
            wv[t] = __ldg((const float4*)(wq + t * CIN + cb));
#pragma unroll
        for (int iy = 0; iy < SP; iy++) {
            const float* rp = g_buf + in_off + ((long)(b * SP + iy) * SP) * CST + cb;
#pragma unroll
            for (int ix = 0; ix < SP; ix++) {
                float4 a = __ldg((const float4*)(rp + ix * CST));
#pragma unroll
                for (int oy = 0; oy < 2; oy++) {
                    int dy = iy - oy;
                    if (dy < 0 || dy > 2) continue;
#pragma unroll
                    for (int ox = 0; ox < 2; ox++) {
                        int dx = ix - ox;
                        if (dx < 0 || dx > 2) continue;
                        float4 wt = wv[dy * 3 + dx];
                        acc[oy][ox] += a.x*wt.x + a.y*wt.y + a.z*wt.z + a.w*wt.w;
                    }
                }
            }
        }
    }
#pragma unroll
    for (int oy = 0; oy < 2; oy++)
#pragma unroll
        for (int ox = 0; ox < 2; ox++)
#pragma unroll
            for (int o = 16; o; o >>= 1)
                acc[oy][ox] += __shfl_xor_sync(0xffffffffu, acc[oy][ox], o);

    if (lane == 0) {
        float thr = __ldg(thrp), leak = __ldg(leakp);
#pragma unroll
        for (int oy = 0; oy < 2; oy++)
#pragma unroll
            for (int ox = 0; ox < 2; ox++) {
                long midx = (((long)b * 2 + oy) * 2 + ox) * COUT + co;
                long oidx = (((long)b * SP + (oy + 1)) * SP + (ox + 1)) * (long)COUT + co;
                g_buf[out_off + oidx] =
                    lif_fire(&g_buf[mem_off + midx], acc[oy][ox], thr, leak);
            }
    }
}

// ---------------- avg-pool 2x2 --------------------------------------------
template<int C, int S, int CI, int CO>   // NCHW(S) -> NCHW(S/2)
__global__ void k_pool_cc(int in_off, int out_off) {
    constexpr int SO = S / 2, RSI = S + 4, ROWSI = S + 2, RSO = SO + 4, ROWSO = SO + 2;
    int idx = blockIdx.x * blockDim.x + threadIdx.x;
    if (idx >= BATCH * C * SO * SO) return;
    int x = idx % SO, y = (idx / SO) % SO;
    int c = (idx / (SO * SO)) % C, b = idx / (SO * SO * C);
    const float* p = g_buf + in_off + ((long)(b * CI + c) * ROWSI + 2 * y + 1) * RSI + 2 * x + 1;
    float v = 0.25f * (p[0] + p[1] + p[RSI] + p[RSI + 1]);
    g_buf[out_off + ((long)(b * CO + c) * ROWSO + y + 1) * RSO + x + 1] = v;
}

template<int C, int S, int CI, int CSTO>  // NCHW(S) -> NHWC(S/2)
__global__ void k_pool_cn(int in_off, int out_off) {
    constexpr int SO = S / 2, RSI = S + 4, ROWSI = S + 2, SPO = SO + 2;
    int idx = blockIdx.x * blockDim.x + threadIdx.x;
    if (idx >= BATCH * C * SO * SO) return;
    int c = idx % C;
    int x = (idx / C) % SO, y = (idx / (C * SO)) % SO, b = idx / (C * SO * SO);
    const float* p = g_buf + in_off + ((long)(b * CI + c) * ROWSI + 2 * y + 1) * RSI + 2 * x + 1;
    float v = 0.25f * (p[0] + p[1] + p[RSI] + p[RSI + 1]);
    g_buf[out_off + (((long)b * SPO + y + 1) * SPO + x + 1) * CSTO + c] = v;
}

template<int C, int S, int CSTI, int CSTO>  // NHWC(S) -> NHWC(S/2)
__global__ void k_pool_nn(int in_off, int out_off) {
    constexpr int SO = S / 2, SPI = S + 2, SPO = SO + 2;
    int idx = blockIdx.x * blockDim.x + threadIdx.x;
    if (idx >= BATCH * C * SO * SO) return;
    int c = idx % C;
    int x = (idx / C) % SO, y = (idx / (C * SO)) % SO, b = idx / (C * SO * SO);
    const float* p = g_buf + in_off + (((long)b * SPI + 2 * y + 1) * SPI + 2 * x + 1) * CSTI + c;
    float v = 0.25f * (p[0] + p[CSTI] + p[(long)SPI * CSTI] + p[(long)(SPI + 1) * CSTI]);
    g_buf[out_off + (((long)b * SPO + y + 1) * SPO + x + 1) * CSTO + c] = v;
}

// ---------------- fully connected: warp per output, 4 batches fused -------
// fc0 reads NHWC padded [4][4][4][512] directly: flat f = c*4 + y*2 + x.
__global__ __launch_bounds__(256)
void k_fc0(const float* __restrict__ W, int mem_off, int out_off,
           const float* __restrict__ thrp, const float* __restrict__ leakp) {
    int gt = blockIdx.x * blockDim.x + threadIdx.x;
    int o = gt >> 5, lane = gt & 31;
    if (o >= 4096) return;
    const float* src = g_buf + OFF_2B;
    float acc[4] = {0.f, 0.f, 0.f, 0.f};
    for (int c = lane; c < 512; c += 32) {
        float4 wv = __ldg((const float4*)(W + (long)o * 2048 + c * 4));
#pragma unroll
        for (int b = 0; b < 4; b++) {
            long base = ((long)(b * 16 + 5)) * 512 + c;   // padded (1,1)
            float a00 = src[base], a01 = src[base + 512];
            float a10 = src[base + 4 * 512], a11 = src[base + 5 * 512];
            acc[b] += wv.x * a00 + wv.y * a01 + wv.z * a10 + wv.w * a11;
        }
    }
#pragma unroll
    for (int b = 0; b < 4; b++)
#pragma unroll
        for (int of = 16; of; of >>= 1)
            acc[b] += __shfl_xor_sync(0xffffffffu, acc[b], of);
    if (lane == 0) {
        float thr = __ldg(thrp), leak = __ldg(leakp);
#pragma unroll
        for (int b = 0; b < 4; b++)
            g_buf[out_off + (long)b * 4096 + o] =
                lif_fire(&g_buf[mem_off + (long)b * 4096 + o], acc[b], thr, leak);
    }
}

template<int KD>
__global__ __launch_bounds__(256)
void k_fc4(const float* __restrict__ W, int in_off, int mem_off, int out_off,
           const float* __restrict__ thrp, const float* __restrict__ leakp,
           int OUTN) {
    int gt = blockIdx.x * blockDim.x + threadIdx.x;
    int o = gt >> 5, lane = gt & 31;
    if (o >= OUTN) return;
    const float4* wp = (const float4*)(W + (long)o * KD);
    const float4* ip = (const float4*)(g_buf + in_off);
    float acc[4] = {0.f, 0.f, 0.f, 0.f};
    for (int k = lane; k < KD / 4; k += 32) {
        float4 wv = __ldg(wp + k);
#pragma unroll
        for (int b = 0; b < 4; b++) {
            float4 a = ip[b * (KD / 4) + k];
            acc[b] += wv.x * a.x + wv.y * a.y + wv.z * a.z + wv.w * a.w;
        }
    }
#pragma unroll
    for (int b = 0; b < 4; b++)
#pragma unroll
        for (int of = 16; of; of >>= 1)
            acc[b] += __shfl_xor_sync(0xffffffffu, acc[b], of);
    if (lane == 0) {
        float thr = __ldg(thrp), leak = __ldg(leakp);
#pragma unroll
        for (int b = 0; b < 4; b++)
            g_buf[out_off + (long)b * OUTN + o] =
                lif_fire(&g_buf[mem_off + (long)b * OUTN + o], acc[b], thr, leak);
    }
}

__global__ void k_logits4(const float* __restrict__ W, int in_off,
                          float* __restrict__ dout) {
    int gt = blockIdx.x * blockDim.x + threadIdx.x;
    int o = gt >> 5, lane = gt & 31;
    if (o >= 10) return;
    const float4* wp = (const float4*)(W + (long)o * 4096);
    const float4* ip = (const float4*)(g_buf + in_off);
    float acc[4] = {0.f, 0.f, 0.f, 0.f};
    for (int k = lane; k < 1024; k += 32) {
        float4 wv = __ldg(wp + k);
#pragma unroll
        for (int b = 0; b < 4; b++) {
            float4 a = ip[b * 1024 + k];
            acc[b] += wv.x * a.x + wv.y * a.y + wv.z * a.z + wv.w * a.w;
        }
    }
#pragma unroll
    for (int b = 0; b < 4; b++)
#pragma unroll
        for (int of = 16; of; of >>= 1)
            acc[b] += __shfl_xor_sync(0xffffffffu, acc[b], of);
    if (lane == 0)
#pragma unroll
        for (int b = 0; b < 4; b++)
            dout[b * 10 + o] += acc[b];
}

// ---------------- launch --------------------------------------------------
static inline int gup(long n, int b) { return (int)((n + b - 1) / b); }

extern "C" void kernel_launch(void* const* d_in, const int* in_sizes, int n_in,
                              void* d_out, int out_size) {
    const float* x = (const float*)d_in[0];
    const float* w[13];
    for (int i = 0; i < 13; i++) w[i] = (const float*)d_in[1 + i];
    const float* fc0w = (const float*)d_in[14];
    const float* fc1w = (const float*)d_in[15];
    const float* fc2w = (const float*)d_in[16];
    const float* thr  = (const float*)d_in[17];
    const float* leak = (const float*)d_in[18];
    float* out = (float*)d_out;

    k_zero<<<gup(TOTAL_BUF, 256), 256>>>(out);
    k_pad_x<<<gup(BATCH * 3 * 1024, 256), 256>>>(x);

    WP wp;
    for (int i = 0; i < 9; i++) wp.p[i] = w[4 + i];
    k_wtrans_all<<<dim3(512, 9), 256>>>(wp);

    for (int t = 0; t < 3; t++) {
        // ---- 32x32, NCHW ----
        k_conv_T<3, 3, 32, 64, 4><<<64 * 4, 256>>>(
            OFF_X, w[0], M0, OFF_32A, thr + 0, leak + 0);
        k_conv_T<64, 64, 32, 64, 4><<<64 * 4, 256>>>(
            OFF_32A, w[1], M1, OFF_32B, thr + 1, leak + 1);
        k_pool_cc<64, 32, 64, 128><<<gup(4L * 64 * 16 * 16, 256), 256>>>(OFF_32B, OFF_16A);

        // ---- 16x16, NCHW ----
        k_conv_T<64, 128, 16, 128, 1><<<128, 256>>>(
            OFF_16A, w[2], M2, OFF_16B, thr + 2, leak + 2);
        k_conv_T<128, 128, 16, 128, 1><<<128, 256>>>(
            OFF_16B, w[3], M3, OFF_16A, thr + 3, leak + 3);
        k_pool_cn<128, 16, 128, 256><<<gup(4L * 128 * 8 * 8, 256), 256>>>(OFF_16A, OFF_8A);

        // ---- 8x8, NHWC ----
        k_conv_W<128, 256, 8, 256><<<gup(4L * 256 * 8 * 32, 256), 256>>>(
            OFF_8A, WT4, M4, OFF_8B, thr + 4, leak + 4);
        k_conv_W<256, 256, 8, 256><<<gup(4L * 256 * 8 * 32, 256), 256>>>(
            OFF_8B, WT5, M5, OFF_8A, thr + 5, leak + 5);
        k_conv_W<256, 256, 8, 256><<<gup(4L * 256 * 8 * 32, 256), 256>>>(
            OFF_8A, WT6, M6, OFF_8B, thr + 6, leak + 6);
        k_pool_nn<256, 8, 256, 512><<<gup(4L * 256 * 4 * 4, 256), 256>>>(OFF_8B, OFF_4A);

        // ---- 4x4, NHWC ----
        k_conv_W<256, 512, 4, 512><<<gup(4L * 512 * 4 * 32, 256), 256>>>(
            OFF_4A, WT7, M7, OFF_4B, thr + 7, leak + 7);
        k_conv_W<512, 512, 4, 512><<<gup(4L * 512 * 4 * 32, 256), 256>>>(
            OFF_4B, WT8, M8, OFF_4A, thr + 8, leak + 8);
        k_conv_W<512, 512, 4, 512><<<gup(4L * 512 * 4 * 32, 256), 256>>>(
            OFF_4A, WT9, M9, OFF_4B, thr + 9, leak + 9);
        k_pool_nn<512, 4, 512, 512><<<gup(4L * 512 * 2 * 2, 256), 256>>>(OFF_4B, OFF_2A);

        // ---- 2x2, NHWC, full-image warps ----
        k_conv_W2<512><<<gup(4L * 512 * 32, 256), 256>>>(
            OFF_2A, WT10, M10, OFF_2B, thr + 10, leak + 10);
        k_conv_W2<512><<<gup(4L * 512 * 32, 256), 256>>>(
            OFF_2B, WT11, M11, OFF_2A, thr + 11, leak + 11);
        k_conv_W2<512><<<gup(4L * 512 * 32, 256), 256>>>(
            OFF_2A, WT12, M12, OFF_2B, thr + 12, leak + 12);

        // ---- classifier ----
        k_fc0<<<gup(4096L * 32, 256), 256>>>(fc0w, MF0, OFF_FCS0, thr + 13, leak + 13);
        k_fc4<4096><<<gup(4096L * 32, 256), 256>>>(
            fc1w, OFF_FCS0, MF1, OFF_FCS1, thr + 14, leak + 14, 4096);
        k_logits4<<<2, 256>>>(fc2w, OFF_FCS1, out);
    }
}